// round 1
// baseline (speedup 1.0000x reference)
#include <cuda_runtime.h>
#include <cstdint>

// NormAttention: S = Q@K^T, S[mask==0]=-1e4, O = S@V, LayerNorm_D(O)*gamma+beta
// B=2,H=12 (BH=24), L=2048, D=64. fp32 in/out; tf32 tensor cores internally
// (-10000 is EXACTLY representable in tf32; bf16 would break the 1e-3 gate).

namespace {

constexpr int Ldim = 2048;
constexpr int Dd   = 64;
constexpr int BM   = 128;   // Q rows per CTA
constexpr int BN   = 64;    // K/V rows per k-tile
constexpr int TSTRIDE = Dd + 4;   // 68: smem row stride (banks shift by 4 per row)
constexpr int SSTRIDE = BN + 4;   // 68

__device__ __forceinline__ float to_tf32(float x) {
    uint32_t u;
    asm("cvt.rna.tf32.f32 %0, %1;" : "=r"(u) : "f"(x));
    return __uint_as_float(u);
}

__device__ __forceinline__ void mma_tf32(float c[4], const uint32_t a[4], const uint32_t b[2]) {
    asm volatile(
        "mma.sync.aligned.m16n8k8.row.col.f32.tf32.tf32.f32 "
        "{%0,%1,%2,%3}, {%4,%5,%6,%7}, {%8,%9}, {%0,%1,%2,%3};\n"
        : "+f"(c[0]), "+f"(c[1]), "+f"(c[2]), "+f"(c[3])
        : "r"(a[0]), "r"(a[1]), "r"(a[2]), "r"(a[3]),
          "r"(b[0]), "r"(b[1]));
}

} // namespace

__global__ __launch_bounds__(256, 1)
void norm_attn_kernel(const float* __restrict__ Q, const float* __restrict__ K,
                      const float* __restrict__ V, const int*  __restrict__ mask,
                      const float* __restrict__ gamma, const float* __restrict__ beta,
                      float* __restrict__ out)
{
    extern __shared__ float smem[];
    float* Qs = smem;                    // BM x TSTRIDE
    float* Ks = Qs + BM * TSTRIDE;       // BN x TSTRIDE
    float* Vs = Ks + BN * TSTRIDE;       // BN x TSTRIDE
    float* Ss = Vs + BN * TSTRIDE;       // BM x SSTRIDE (also O staging)

    const int bh  = blockIdx.y;
    const int qt  = blockIdx.x;
    const int tid = threadIdx.x;
    const int warp = tid >> 5;
    const int lane = tid & 31;
    const int g  = lane >> 2;   // groupID
    const int tg = lane & 3;    // thread-in-group
    const int wm = warp >> 1;   // 0..3 : M slice (32 rows)
    const int wn = warp & 1;    // 0..1 : N slice (32 cols)

    const size_t bh_off = (size_t)bh * Ldim * Dd;
    const float* qptr = Q + bh_off + (size_t)qt * BM * Dd;

    // ---- Load Q tile (tf32-rounded) ----
    for (int i = tid; i < BM * (Dd / 4); i += 256) {
        int r = i >> 4, c = (i & 15) << 2;
        float4 t = *reinterpret_cast<const float4*>(qptr + r * Dd + c);
        float* dst = Qs + r * TSTRIDE + c;
        dst[0] = to_tf32(t.x); dst[1] = to_tf32(t.y);
        dst[2] = to_tf32(t.z); dst[3] = to_tf32(t.w);
    }

    // O accumulator: warp tile 32x32 -> 2 (M16) x 4 (N8) mma tiles
    float o[2][4][4];
    #pragma unroll
    for (int mi = 0; mi < 2; ++mi)
        #pragma unroll
        for (int nj = 0; nj < 4; ++nj)
            #pragma unroll
            for (int r = 0; r < 4; ++r) o[mi][nj][r] = 0.0f;

    const int row0 = wm * 32;   // warp local M offset
    const int col0 = wn * 32;   // warp local N offset

    for (int kt = 0; kt < Ldim / BN; ++kt) {
        __syncthreads();   // prev GEMM2 done reading Ss/Vs
        const float* kptr = K + bh_off + (size_t)kt * BN * Dd;
        const float* vptr = V + bh_off + (size_t)kt * BN * Dd;
        for (int i = tid; i < BN * (Dd / 4); i += 256) {
            int r = i >> 4, c = (i & 15) << 2;
            float4 tk = *reinterpret_cast<const float4*>(kptr + r * Dd + c);
            float4 tv = *reinterpret_cast<const float4*>(vptr + r * Dd + c);
            float* dk = Ks + r * TSTRIDE + c;
            float* dv = Vs + r * TSTRIDE + c;
            dk[0] = to_tf32(tk.x); dk[1] = to_tf32(tk.y);
            dk[2] = to_tf32(tk.z); dk[3] = to_tf32(tk.w);
            dv[0] = to_tf32(tv.x); dv[1] = to_tf32(tv.y);
            dv[2] = to_tf32(tv.z); dv[3] = to_tf32(tv.w);
        }
        __syncthreads();

        // ---- GEMM1: S(warp 32x32) = Q_tile @ K_tile^T  (K-dim = D = 64) ----
        float s[2][4][4];
        #pragma unroll
        for (int mi = 0; mi < 2; ++mi)
            #pragma unroll
            for (int nj = 0; nj < 4; ++nj)
                #pragma unroll
                for (int r = 0; r < 4; ++r) s[mi][nj][r] = 0.0f;

        #pragma unroll
        for (int kk = 0; kk < Dd; kk += 8) {
            uint32_t a[2][4], b[4][2];
            #pragma unroll
            for (int mi = 0; mi < 2; ++mi) {
                const float* p  = Qs + (row0 + mi * 16 + g) * TSTRIDE + kk + tg;
                const float* p8 = p + 8 * TSTRIDE;
                a[mi][0] = __float_as_uint(p[0]);
                a[mi][1] = __float_as_uint(p8[0]);
                a[mi][2] = __float_as_uint(p[4]);
                a[mi][3] = __float_as_uint(p8[4]);
            }
            #pragma unroll
            for (int nj = 0; nj < 4; ++nj) {
                const float* p = Ks + (col0 + nj * 8 + g) * TSTRIDE + kk + tg;
                b[nj][0] = __float_as_uint(p[0]);
                b[nj][1] = __float_as_uint(p[4]);
            }
            #pragma unroll
            for (int mi = 0; mi < 2; ++mi)
                #pragma unroll
                for (int nj = 0; nj < 4; ++nj)
                    mma_tf32(s[mi][nj], a[mi], b[nj]);
        }

        // ---- Mask in fp32, re-quantize to tf32, stage S in smem ----
        #pragma unroll
        for (int mi = 0; mi < 2; ++mi) {
            #pragma unroll
            for (int nj = 0; nj < 4; ++nj) {
                const int rl = row0 + mi * 16 + g;          // local row
                const int cl = col0 + nj * 8 + 2 * tg;      // local col (even)
                const int gq = qt * BM + rl;
                const int gc = kt * BN + cl;
                int2 m0 = *reinterpret_cast<const int2*>(mask + (size_t)gq * Ldim + gc);
                int2 m1 = *reinterpret_cast<const int2*>(mask + (size_t)(gq + 8) * Ldim + gc);
                float v0 = (m0.x != 0) ? s[mi][nj][0] : -10000.0f;
                float v1 = (m0.y != 0) ? s[mi][nj][1] : -10000.0f;
                float v2 = (m1.x != 0) ? s[mi][nj][2] : -10000.0f;
                float v3 = (m1.y != 0) ? s[mi][nj][3] : -10000.0f;
                Ss[rl * SSTRIDE + cl]           = to_tf32(v0);
                Ss[rl * SSTRIDE + cl + 1]       = to_tf32(v1);
                Ss[(rl + 8) * SSTRIDE + cl]     = to_tf32(v2);
                Ss[(rl + 8) * SSTRIDE + cl + 1] = to_tf32(v3);
            }
        }
        __syncthreads();

        // ---- GEMM2: O(warp 32x32) += S_tile @ V_tile  (K-dim = BN = 64) ----
        #pragma unroll
        for (int kk = 0; kk < BN; kk += 8) {
            uint32_t a[2][4], b[4][2];
            #pragma unroll
            for (int mi = 0; mi < 2; ++mi) {
                const float* p  = Ss + (row0 + mi * 16 + g) * SSTRIDE + kk + tg;
                const float* p8 = p + 8 * SSTRIDE;
                a[mi][0] = __float_as_uint(p[0]);
                a[mi][1] = __float_as_uint(p8[0]);
                a[mi][2] = __float_as_uint(p[4]);
                a[mi][3] = __float_as_uint(p8[4]);
            }
            #pragma unroll
            for (int nj = 0; nj < 4; ++nj) {
                const float* p = Vs + (kk + tg) * TSTRIDE + col0 + nj * 8 + g;
                b[nj][0] = __float_as_uint(p[0]);
                b[nj][1] = __float_as_uint(p[4 * TSTRIDE]);
            }
            #pragma unroll
            for (int mi = 0; mi < 2; ++mi)
                #pragma unroll
                for (int nj = 0; nj < 4; ++nj)
                    mma_tf32(o[mi][nj], a[mi], b[nj]);
        }
    }

    // ---- Stage O in smem (reuse Ss), then per-row LayerNorm over D=64 ----
    __syncthreads();
    #pragma unroll
    for (int mi = 0; mi < 2; ++mi) {
        #pragma unroll
        for (int nj = 0; nj < 4; ++nj) {
            const int rl = row0 + mi * 16 + g;
            const int cl = col0 + nj * 8 + 2 * tg;
            Ss[rl * SSTRIDE + cl]           = o[mi][nj][0];
            Ss[rl * SSTRIDE + cl + 1]       = o[mi][nj][1];
            Ss[(rl + 8) * SSTRIDE + cl]     = o[mi][nj][2];
            Ss[(rl + 8) * SSTRIDE + cl + 1] = o[mi][nj][3];
        }
    }
    __syncthreads();

    if (tid < BM) {
        const float* rowp = Ss + tid * SSTRIDE;
        float x[Dd];
        float sum = 0.0f;
        #pragma unroll
        for (int c = 0; c < Dd; c += 4) {
            float4 t = *reinterpret_cast<const float4*>(rowp + c);
            x[c] = t.x; x[c + 1] = t.y; x[c + 2] = t.z; x[c + 3] = t.w;
            sum += t.x + t.y + t.z + t.w;
        }
        const float mean = sum * (1.0f / Dd);
        float var = 0.0f;
        #pragma unroll
        for (int c = 0; c < Dd; ++c) {
            float d = x[c] - mean;
            var += d * d;
        }
        var *= (1.0f / Dd);
        const float inv = rsqrtf(var + 1e-12f);
        float* op = out + bh_off + (size_t)(qt * BM + tid) * Dd;
        #pragma unroll
        for (int c = 0; c < Dd; ++c)
            op[c] = (x[c] - mean) * inv * __ldg(gamma + c) + __ldg(beta + c);
    }
}

extern "C" void kernel_launch(void* const* d_in, const int* in_sizes, int n_in,
                              void* d_out, int out_size)
{
    const float* q     = (const float*)d_in[0];
    const float* k     = (const float*)d_in[1];
    const float* v     = (const float*)d_in[2];
    const int*   mask  = (const int*)  d_in[3];
    const float* gamma = (const float*)d_in[4];
    const float* beta  = (const float*)d_in[5];
    float* out = (float*)d_out;

    const int bh_count = in_sizes[0] / (Ldim * Dd);   // 24

    constexpr int smem_bytes =
        (BM * TSTRIDE + 2 * BN * TSTRIDE + BM * SSTRIDE) * (int)sizeof(float); // ~102 KB
    cudaFuncSetAttribute(norm_attn_kernel,
                         cudaFuncAttributeMaxDynamicSharedMemorySize, smem_bytes);

    dim3 grid(Ldim / BM, bh_count);
    norm_attn_kernel<<<grid, 256, smem_bytes>>>(q, k, v, mask, gamma, beta, out);
}

// round 2
// speedup vs baseline: 1.0013x; 1.0013x over previous
#include <cuda_runtime.h>
#include <cstdint>

// NormAttention: S = Q@K^T, S[mask==0]=-1e4, O = S@V, LayerNorm_D(O)*gamma+beta
// B=2,H=12 (BH=24), L=2048, D=64. fp32 in/out; tf32 tensor cores internally
// (-10000 is EXACTLY representable in tf32; bf16 would break the 1e-3 gate).

namespace {

constexpr int Ldim = 2048;
constexpr int Dd   = 64;
constexpr int BM   = 128;   // Q rows per CTA
constexpr int BN   = 64;    // K/V rows per k-tile
constexpr int TSTRIDE = Dd + 4;   // 68: smem row stride (banks shift by 4 per row)
constexpr int SSTRIDE = BN + 4;   // 68

__device__ __forceinline__ float to_tf32(float x) {
    uint32_t u;
    asm("cvt.rna.tf32.f32 %0, %1;" : "=r"(u) : "f"(x));
    return __uint_as_float(u);
}

__device__ __forceinline__ void mma_tf32(float c[4], const uint32_t a[4], const uint32_t b[2]) {
    asm volatile(
        "mma.sync.aligned.m16n8k8.row.col.f32.tf32.tf32.f32 "
        "{%0,%1,%2,%3}, {%4,%5,%6,%7}, {%8,%9}, {%0,%1,%2,%3};\n"
        : "+f"(c[0]), "+f"(c[1]), "+f"(c[2]), "+f"(c[3])
        : "r"(a[0]), "r"(a[1]), "r"(a[2]), "r"(a[3]),
          "r"(b[0]), "r"(b[1]));
}

} // namespace

__global__ __launch_bounds__(256, 1)
void norm_attn_kernel(const float* __restrict__ Q, const float* __restrict__ K,
                      const float* __restrict__ V, const int*  __restrict__ mask,
                      const float* __restrict__ gamma, const float* __restrict__ beta,
                      float* __restrict__ out)
{
    extern __shared__ float smem[];
    float* Qs = smem;                    // BM x TSTRIDE
    float* Ks = Qs + BM * TSTRIDE;       // BN x TSTRIDE
    float* Vs = Ks + BN * TSTRIDE;       // BN x TSTRIDE
    float* Ss = Vs + BN * TSTRIDE;       // BM x SSTRIDE (also O staging)

    const int bh  = blockIdx.y;
    const int qt  = blockIdx.x;
    const int tid = threadIdx.x;
    const int warp = tid >> 5;
    const int lane = tid & 31;
    const int g  = lane >> 2;   // groupID
    const int tg = lane & 3;    // thread-in-group
    const int wm = warp >> 1;   // 0..3 : M slice (32 rows)
    const int wn = warp & 1;    // 0..1 : N slice (32 cols)

    const size_t bh_off = (size_t)bh * Ldim * Dd;
    const float* qptr = Q + bh_off + (size_t)qt * BM * Dd;

    // ---- Load Q tile (tf32-rounded) ----
    for (int i = tid; i < BM * (Dd / 4); i += 256) {
        int r = i >> 4, c = (i & 15) << 2;
        float4 t = *reinterpret_cast<const float4*>(qptr + r * Dd + c);
        float* dst = Qs + r * TSTRIDE + c;
        dst[0] = to_tf32(t.x); dst[1] = to_tf32(t.y);
        dst[2] = to_tf32(t.z); dst[3] = to_tf32(t.w);
    }

    // O accumulator: warp tile 32x32 -> 2 (M16) x 4 (N8) mma tiles
    float o[2][4][4];
    #pragma unroll
    for (int mi = 0; mi < 2; ++mi)
        #pragma unroll
        for (int nj = 0; nj < 4; ++nj)
            #pragma unroll
            for (int r = 0; r < 4; ++r) o[mi][nj][r] = 0.0f;

    const int row0 = wm * 32;   // warp local M offset
    const int col0 = wn * 32;   // warp local N offset

    for (int kt = 0; kt < Ldim / BN; ++kt) {
        __syncthreads();   // prev GEMM2 done reading Ss/Vs
        const float* kptr = K + bh_off + (size_t)kt * BN * Dd;
        const float* vptr = V + bh_off + (size_t)kt * BN * Dd;
        for (int i = tid; i < BN * (Dd / 4); i += 256) {
            int r = i >> 4, c = (i & 15) << 2;
            float4 tk = *reinterpret_cast<const float4*>(kptr + r * Dd + c);
            float4 tv = *reinterpret_cast<const float4*>(vptr + r * Dd + c);
            float* dk = Ks + r * TSTRIDE + c;
            float* dv = Vs + r * TSTRIDE + c;
            dk[0] = to_tf32(tk.x); dk[1] = to_tf32(tk.y);
            dk[2] = to_tf32(tk.z); dk[3] = to_tf32(tk.w);
            dv[0] = to_tf32(tv.x); dv[1] = to_tf32(tv.y);
            dv[2] = to_tf32(tv.z); dv[3] = to_tf32(tv.w);
        }
        __syncthreads();

        // ---- GEMM1: S(warp 32x32) = Q_tile @ K_tile^T  (K-dim = D = 64) ----
        float s[2][4][4];
        #pragma unroll
        for (int mi = 0; mi < 2; ++mi)
            #pragma unroll
            for (int nj = 0; nj < 4; ++nj)
                #pragma unroll
                for (int r = 0; r < 4; ++r) s[mi][nj][r] = 0.0f;

        #pragma unroll
        for (int kk = 0; kk < Dd; kk += 8) {
            uint32_t a[2][4], b[4][2];
            #pragma unroll
            for (int mi = 0; mi < 2; ++mi) {
                const float* p  = Qs + (row0 + mi * 16 + g) * TSTRIDE + kk + tg;
                const float* p8 = p + 8 * TSTRIDE;
                a[mi][0] = __float_as_uint(p[0]);
                a[mi][1] = __float_as_uint(p8[0]);
                a[mi][2] = __float_as_uint(p[4]);
                a[mi][3] = __float_as_uint(p8[4]);
            }
            #pragma unroll
            for (int nj = 0; nj < 4; ++nj) {
                const float* p = Ks + (col0 + nj * 8 + g) * TSTRIDE + kk + tg;
                b[nj][0] = __float_as_uint(p[0]);
                b[nj][1] = __float_as_uint(p[4]);
            }
            #pragma unroll
            for (int mi = 0; mi < 2; ++mi)
                #pragma unroll
                for (int nj = 0; nj < 4; ++nj)
                    mma_tf32(s[mi][nj], a[mi], b[nj]);
        }

        // ---- Mask in fp32, re-quantize to tf32, stage S in smem ----
        #pragma unroll
        for (int mi = 0; mi < 2; ++mi) {
            #pragma unroll
            for (int nj = 0; nj < 4; ++nj) {
                const int rl = row0 + mi * 16 + g;          // local row
                const int cl = col0 + nj * 8 + 2 * tg;      // local col (even)
                const int gq = qt * BM + rl;
                const int gc = kt * BN + cl;
                int2 m0 = *reinterpret_cast<const int2*>(mask + (size_t)gq * Ldim + gc);
                int2 m1 = *reinterpret_cast<const int2*>(mask + (size_t)(gq + 8) * Ldim + gc);
                float v0 = (m0.x != 0) ? s[mi][nj][0] : -10000.0f;
                float v1 = (m0.y != 0) ? s[mi][nj][1] : -10000.0f;
                float v2 = (m1.x != 0) ? s[mi][nj][2] : -10000.0f;
                float v3 = (m1.y != 0) ? s[mi][nj][3] : -10000.0f;
                Ss[rl * SSTRIDE + cl]           = to_tf32(v0);
                Ss[rl * SSTRIDE + cl + 1]       = to_tf32(v1);
                Ss[(rl + 8) * SSTRIDE + cl]     = to_tf32(v2);
                Ss[(rl + 8) * SSTRIDE + cl + 1] = to_tf32(v3);
            }
        }
        __syncthreads();

        // ---- GEMM2: O(warp 32x32) += S_tile @ V_tile  (K-dim = BN = 64) ----
        #pragma unroll
        for (int kk = 0; kk < BN; kk += 8) {
            uint32_t a[2][4], b[4][2];
            #pragma unroll
            for (int mi = 0; mi < 2; ++mi) {
                const float* p  = Ss + (row0 + mi * 16 + g) * SSTRIDE + kk + tg;
                const float* p8 = p + 8 * SSTRIDE;
                a[mi][0] = __float_as_uint(p[0]);
                a[mi][1] = __float_as_uint(p8[0]);
                a[mi][2] = __float_as_uint(p[4]);
                a[mi][3] = __float_as_uint(p8[4]);
            }
            #pragma unroll
            for (int nj = 0; nj < 4; ++nj) {
                const float* p = Vs + (kk + tg) * TSTRIDE + col0 + nj * 8 + g;
                b[nj][0] = __float_as_uint(p[0]);
                b[nj][1] = __float_as_uint(p[4 * TSTRIDE]);
            }
            #pragma unroll
            for (int mi = 0; mi < 2; ++mi)
                #pragma unroll
                for (int nj = 0; nj < 4; ++nj)
                    mma_tf32(o[mi][nj], a[mi], b[nj]);
        }
    }

    // ---- Stage O in smem (reuse Ss), then per-row LayerNorm over D=64 ----
    __syncthreads();
    #pragma unroll
    for (int mi = 0; mi < 2; ++mi) {
        #pragma unroll
        for (int nj = 0; nj < 4; ++nj) {
            const int rl = row0 + mi * 16 + g;
            const int cl = col0 + nj * 8 + 2 * tg;
            Ss[rl * SSTRIDE + cl]           = o[mi][nj][0];
            Ss[rl * SSTRIDE + cl + 1]       = o[mi][nj][1];
            Ss[(rl + 8) * SSTRIDE + cl]     = o[mi][nj][2];
            Ss[(rl + 8) * SSTRIDE + cl + 1] = o[mi][nj][3];
        }
    }
    __syncthreads();

    if (tid < BM) {
        const float* rowp = Ss + tid * SSTRIDE;
        float x[Dd];
        float sum = 0.0f;
        #pragma unroll
        for (int c = 0; c < Dd; c += 4) {
            float4 t = *reinterpret_cast<const float4*>(rowp + c);
            x[c] = t.x; x[c + 1] = t.y; x[c + 2] = t.z; x[c + 3] = t.w;
            sum += t.x + t.y + t.z + t.w;
        }
        const float mean = sum * (1.0f / Dd);
        float var = 0.0f;
        #pragma unroll
        for (int c = 0; c < Dd; ++c) {
            float d = x[c] - mean;
            var += d * d;
        }
        var *= (1.0f / Dd);
        const float inv = rsqrtf(var + 1e-12f);
        float* op = out + bh_off + (size_t)(qt * BM + tid) * Dd;
        #pragma unroll
        for (int c = 0; c < Dd; ++c)
            op[c] = (x[c] - mean) * inv * __ldg(gamma + c) + __ldg(beta + c);
    }
}

extern "C" void kernel_launch(void* const* d_in, const int* in_sizes, int n_in,
                              void* d_out, int out_size)
{
    const float* q     = (const float*)d_in[0];
    const float* k     = (const float*)d_in[1];
    const float* v     = (const float*)d_in[2];
    const int*   mask  = (const int*)  d_in[3];
    const float* gamma = (const float*)d_in[4];
    const float* beta  = (const float*)d_in[5];
    float* out = (float*)d_out;

    const int bh_count = in_sizes[0] / (Ldim * Dd);   // 24

    constexpr int smem_bytes =
        (BM * TSTRIDE + 2 * BN * TSTRIDE + BM * SSTRIDE) * (int)sizeof(float); // ~102 KB
    cudaFuncSetAttribute(norm_attn_kernel,
                         cudaFuncAttributeMaxDynamicSharedMemorySize, smem_bytes);

    dim3 grid(Ldim / BM, bh_count);
    norm_attn_kernel<<<grid, 256, smem_bytes>>>(q, k, v, mask, gamma, beta, out);
}

// round 4
// speedup vs baseline: 1.8774x; 1.8749x over previous
#include <cuda_runtime.h>
#include <cstdint>

// NormAttention, sm_103 (no tcgen05 on this toolchain target — verified R3):
// optimized legacy-path tf32 mma.sync. 512 thr / 16 warps, warp tile 32x16,
// double-buffered cp.async K/V from pre-tf32'd scratch, fused LayerNorm.

namespace {
constexpr int Ldim = 2048, Dd = 64, BM = 128, BN = 64, NT = Ldim / BN;
constexpr int STR  = 68;                 // smem row stride (floats), conflict-free
constexpr int QS = 0;                    // 128 x STR
constexpr int KS = QS + BM * STR;        // 2 x 64 x STR (double buffer)
constexpr int VS = KS + 2 * BN * STR;    // 2 x 64 x STR
constexpr int SS = VS + 2 * BN * STR;    // 128 x STR (S tile / O staging)
constexpr int SMEMF = SS + BM * STR;     // 34816 floats = 139264 B
constexpr int BUFF = BN * STR;           // 4352 floats per K/V buffer

__device__ __forceinline__ float tf(float x) {
    uint32_t u; asm("cvt.rna.tf32.f32 %0,%1;" : "=r"(u) : "f"(x));
    return __uint_as_float(u);
}
__device__ __forceinline__ void mma8(float c[4], const uint32_t a[4], const uint32_t b[2]) {
    asm volatile(
        "mma.sync.aligned.m16n8k8.row.col.f32.tf32.tf32.f32 "
        "{%0,%1,%2,%3},{%4,%5,%6,%7},{%8,%9},{%0,%1,%2,%3};"
        : "+f"(c[0]), "+f"(c[1]), "+f"(c[2]), "+f"(c[3])
        : "r"(a[0]), "r"(a[1]), "r"(a[2]), "r"(a[3]), "r"(b[0]), "r"(b[1]));
}
__device__ __forceinline__ void cpa16(uint32_t s, const void* g) {
    asm volatile("cp.async.cg.shared.global [%0],[%1],16;" :: "r"(s), "l"(g));
}
__device__ __forceinline__ void cp_commit() { asm volatile("cp.async.commit_group;"); }
__device__ __forceinline__ void cp_wait0()  { asm volatile("cp.async.wait_group 0;"); }
} // namespace

__device__ __align__(16) float g_kt[24 * Ldim * Dd];   // tf32-rounded K
__device__ __align__(16) float g_vt[24 * Ldim * Dd];   // tf32-rounded V

__global__ void cvt_kv_k(const float* __restrict__ K, const float* __restrict__ V, int n4) {
    int i = blockIdx.x * blockDim.x + threadIdx.x;
    if (i >= n4) return;
    float4 a = ((const float4*)K)[i];
    ((float4*)g_kt)[i] = make_float4(tf(a.x), tf(a.y), tf(a.z), tf(a.w));
    float4 b = ((const float4*)V)[i];
    ((float4*)g_vt)[i] = make_float4(tf(b.x), tf(b.y), tf(b.z), tf(b.w));
}

__global__ __launch_bounds__(512, 1)
void attn_k(const float* __restrict__ Q, const int* __restrict__ mask,
            const float* __restrict__ gamma, const float* __restrict__ beta,
            float* __restrict__ out)
{
    extern __shared__ float sm[];
    const int tid = threadIdx.x, warp = tid >> 5, lane = tid & 31;
    const int g = lane >> 2, tg = lane & 3;
    const int wm = warp >> 2, wn = warp & 3;        // 4x4 warp grid
    const int row0 = wm * 32, col0 = wn * 16;       // warp tile 32x16
    const int qt = blockIdx.x, bh = blockIdx.y;
    const size_t bho = (size_t)bh * Ldim * Dd;
    const uint32_t sb = (uint32_t)__cvta_generic_to_shared(sm);

    // ---- stage Q (tf32) ----
    const float* qp = Q + bho + (size_t)qt * BM * Dd;
    #pragma unroll
    for (int j = 0; j < 4; ++j) {
        int idx = tid + j * 512, r = idx >> 4, c = (idx & 15) << 2;
        float4 t = *(const float4*)(qp + (size_t)r * Dd + c);
        *(float4*)(sm + QS + r * STR + c) = make_float4(tf(t.x), tf(t.y), tf(t.z), tf(t.w));
    }
    // ---- prefetch k-tile 0 ----
    {
        const float* kp = g_kt + bho;
        const float* vp = g_vt + bho;
        #pragma unroll
        for (int j = 0; j < 2; ++j) {
            int ch = tid + j * 512, r = ch >> 4, c = (ch & 15) << 2;
            cpa16(sb + (uint32_t)(KS + r * STR + c) * 4u, kp + (size_t)r * Dd + c);
            cpa16(sb + (uint32_t)(VS + r * STR + c) * 4u, vp + (size_t)r * Dd + c);
        }
        cp_commit();
    }

    float o[2][2][4] = {};

    for (int kt = 0; kt < NT; ++kt) {
        const int buf = kt & 1;
        cp_wait0();
        __syncthreads();   // tile kt resident; prev GEMM2 done (Ss, V[buf^1] free)

        if (kt + 1 < NT) {  // prefetch next tile into other buffer (overlaps GEMMs)
            const float* kp = g_kt + bho + (size_t)(kt + 1) * BN * Dd;
            const float* vp = g_vt + bho + (size_t)(kt + 1) * BN * Dd;
            const int bo = (buf ^ 1) * BUFF;
            #pragma unroll
            for (int j = 0; j < 2; ++j) {
                int ch = tid + j * 512, r = ch >> 4, c = (ch & 15) << 2;
                cpa16(sb + (uint32_t)(KS + bo + r * STR + c) * 4u, kp + (size_t)r * Dd + c);
                cpa16(sb + (uint32_t)(VS + bo + r * STR + c) * 4u, vp + (size_t)r * Dd + c);
            }
            cp_commit();
        }

        const float* Ksb = sm + KS + buf * BUFF;
        const float* Vsb = sm + VS + buf * BUFF;

        // ---- GEMM1: S(32x16 per warp) = Q @ K^T, k-dim D=64 ----
        float s[2][2][4] = {};
        #pragma unroll
        for (int kk = 0; kk < Dd; kk += 8) {
            uint32_t a[2][4], b[2][2];
            #pragma unroll
            for (int mi = 0; mi < 2; ++mi) {
                const float* p = sm + QS + (row0 + mi * 16 + g) * STR + kk + tg;
                a[mi][0] = __float_as_uint(p[0]);
                a[mi][1] = __float_as_uint(p[8 * STR]);
                a[mi][2] = __float_as_uint(p[4]);
                a[mi][3] = __float_as_uint(p[8 * STR + 4]);
            }
            #pragma unroll
            for (int nj = 0; nj < 2; ++nj) {
                const float* p = Ksb + (col0 + nj * 8 + g) * STR + kk + tg;
                b[nj][0] = __float_as_uint(p[0]);
                b[nj][1] = __float_as_uint(p[4]);
            }
            #pragma unroll
            for (int mi = 0; mi < 2; ++mi)
                #pragma unroll
                for (int nj = 0; nj < 2; ++nj)
                    mma8(s[mi][nj], a[mi], b[nj]);
        }

        // ---- mask (fp32, -1e4 exact in tf32) + requantize + stage S ----
        #pragma unroll
        for (int mi = 0; mi < 2; ++mi) {
            #pragma unroll
            for (int nj = 0; nj < 2; ++nj) {
                const int rl = row0 + mi * 16 + g;
                const int cl = col0 + nj * 8 + 2 * tg;
                const int gq = qt * BM + rl, gc = kt * BN + cl;
                int2 m0 = *(const int2*)(mask + (size_t)gq * Ldim + gc);
                int2 m1 = *(const int2*)(mask + (size_t)(gq + 8) * Ldim + gc);
                float v0 = m0.x ? s[mi][nj][0] : -10000.0f;
                float v1 = m0.y ? s[mi][nj][1] : -10000.0f;
                float v2 = m1.x ? s[mi][nj][2] : -10000.0f;
                float v3 = m1.y ? s[mi][nj][3] : -10000.0f;
                *(float2*)(sm + SS + rl * STR + cl)       = make_float2(tf(v0), tf(v1));
                *(float2*)(sm + SS + (rl + 8) * STR + cl) = make_float2(tf(v2), tf(v3));
            }
        }
        __syncthreads();

        // ---- GEMM2: O(32x16 per warp) += S @ V, k-dim BN=64 ----
        #pragma unroll
        for (int kk = 0; kk < BN; kk += 8) {
            uint32_t a[2][4], b[2][2];
            #pragma unroll
            for (int mi = 0; mi < 2; ++mi) {
                const float* p = sm + SS + (row0 + mi * 16 + g) * STR + kk + tg;
                a[mi][0] = __float_as_uint(p[0]);
                a[mi][1] = __float_as_uint(p[8 * STR]);
                a[mi][2] = __float_as_uint(p[4]);
                a[mi][3] = __float_as_uint(p[8 * STR + 4]);
            }
            #pragma unroll
            for (int nj = 0; nj < 2; ++nj) {
                const float* p = Vsb + (kk + tg) * STR + col0 + nj * 8 + g;
                b[nj][0] = __float_as_uint(p[0]);
                b[nj][1] = __float_as_uint(p[4 * STR]);
            }
            #pragma unroll
            for (int mi = 0; mi < 2; ++mi)
                #pragma unroll
                for (int nj = 0; nj < 2; ++nj)
                    mma8(o[mi][nj], a[mi], b[nj]);
        }
    }

    // ---- stage O into Ss, then LayerNorm over D=64 ----
    __syncthreads();
    #pragma unroll
    for (int mi = 0; mi < 2; ++mi) {
        #pragma unroll
        for (int nj = 0; nj < 2; ++nj) {
            const int rl = row0 + mi * 16 + g;
            const int cl = col0 + nj * 8 + 2 * tg;
            *(float2*)(sm + SS + rl * STR + cl)       = make_float2(o[mi][nj][0], o[mi][nj][1]);
            *(float2*)(sm + SS + (rl + 8) * STR + cl) = make_float2(o[mi][nj][2], o[mi][nj][3]);
        }
    }
    __syncthreads();

    if (tid < BM) {
        const float* rowp = sm + SS + tid * STR;
        float x[Dd]; float sum = 0.0f;
        #pragma unroll
        for (int c = 0; c < Dd; c += 4) {
            float4 t = *(const float4*)(rowp + c);
            x[c] = t.x; x[c+1] = t.y; x[c+2] = t.z; x[c+3] = t.w;
            sum += t.x + t.y + t.z + t.w;
        }
        const float mean = sum * (1.0f / Dd);
        float var = 0.0f;
        #pragma unroll
        for (int c = 0; c < Dd; ++c) { float d = x[c] - mean; var += d * d; }
        const float inv = rsqrtf(var * (1.0f / Dd) + 1e-12f);
        float* op = out + bho + (size_t)(qt * BM + tid) * Dd;
        #pragma unroll
        for (int c = 0; c < Dd; c += 4) {
            float4 t = make_float4(
                (x[c]   - mean) * inv * __ldg(gamma + c)     + __ldg(beta + c),
                (x[c+1] - mean) * inv * __ldg(gamma + c + 1) + __ldg(beta + c + 1),
                (x[c+2] - mean) * inv * __ldg(gamma + c + 2) + __ldg(beta + c + 2),
                (x[c+3] - mean) * inv * __ldg(gamma + c + 3) + __ldg(beta + c + 3));
            *(float4*)(op + c) = t;
        }
    }
}

extern "C" void kernel_launch(void* const* d_in, const int* in_sizes, int n_in,
                              void* d_out, int out_size)
{
    const float* q     = (const float*)d_in[0];
    const float* k     = (const float*)d_in[1];
    const float* v     = (const float*)d_in[2];
    const int*   mask  = (const int*)  d_in[3];
    const float* gamma = (const float*)d_in[4];
    const float* beta  = (const float*)d_in[5];
    float* out = (float*)d_out;

    const int bh = in_sizes[0] / (Ldim * Dd);   // 24
    const int n4 = bh * Ldim * Dd / 4;

    cvt_kv_k<<<(n4 + 255) / 256, 256>>>(k, v, n4);

    cudaFuncSetAttribute(attn_k, cudaFuncAttributeMaxDynamicSharedMemorySize,
                         SMEMF * (int)sizeof(float));
    attn_k<<<dim3(Ldim / BM, bh), 512, SMEMF * (int)sizeof(float)>>>(
        q, mask, gamma, beta, out);
}

// round 5
// speedup vs baseline: 1.9686x; 1.0486x over previous
#include <cuda_runtime.h>
#include <cstdint>

// NormAttention, sm_103 legacy tf32 mma.sync path (tcgen05 unavailable on this
// toolchain target — R3). R5: register-resident S (no smem round-trip between
// GEMM1 and GEMM2). Intra-quad shfl permutes accumulator frags -> A frags.
// Each warp accumulates partial O(32x64) over its 16-wide k-slice; one
// 4-way smem reduction at the end, then fused LayerNorm.

namespace {
constexpr int Ldim = 2048, Dd = 64, BM = 128, BN = 64, NT = Ldim / BN;
constexpr int STR  = 68;                  // padded row stride (floats)
constexpr int QS   = 0;                   // 128 x STR (Q; reused for O-reduce)
constexpr int KS_  = QS + BM * STR;       // 2 x 64 x STR
constexpr int VS_  = KS_ + 2 * BN * STR;  // 2 x 64 x STR
constexpr int SMEMF = VS_ + 2 * BN * STR; // 26112 floats = 104448 B
constexpr int BUFF = BN * STR;

__device__ __forceinline__ float tf(float x) {
    uint32_t u; asm("cvt.rna.tf32.f32 %0,%1;" : "=r"(u) : "f"(x));
    return __uint_as_float(u);
}
__device__ __forceinline__ void mma8(float c[4], const uint32_t a[4], const uint32_t b[2]) {
    asm volatile(
        "mma.sync.aligned.m16n8k8.row.col.f32.tf32.tf32.f32 "
        "{%0,%1,%2,%3},{%4,%5,%6,%7},{%8,%9},{%0,%1,%2,%3};"
        : "+f"(c[0]), "+f"(c[1]), "+f"(c[2]), "+f"(c[3])
        : "r"(a[0]), "r"(a[1]), "r"(a[2]), "r"(a[3]), "r"(b[0]), "r"(b[1]));
}
__device__ __forceinline__ void cpa16(uint32_t s, const void* g) {
    asm volatile("cp.async.cg.shared.global [%0],[%1],16;" :: "r"(s), "l"(g));
}
__device__ __forceinline__ void cp_commit() { asm volatile("cp.async.commit_group;"); }
__device__ __forceinline__ void cp_wait0()  { asm volatile("cp.async.wait_group 0;"); }
} // namespace

__device__ __align__(16) float g_kt[24 * Ldim * Dd];   // tf32-rounded K
__device__ __align__(16) float g_vt[24 * Ldim * Dd];   // tf32-rounded V

__global__ void cvt_kv_k(const float* __restrict__ K, const float* __restrict__ V, int n4) {
    int i = blockIdx.x * blockDim.x + threadIdx.x;
    if (i >= n4) return;
    float4 a = ((const float4*)K)[i];
    ((float4*)g_kt)[i] = make_float4(tf(a.x), tf(a.y), tf(a.z), tf(a.w));
    float4 b = ((const float4*)V)[i];
    ((float4*)g_vt)[i] = make_float4(tf(b.x), tf(b.y), tf(b.z), tf(b.w));
}

__global__ __launch_bounds__(512, 1)
void attn_k(const float* __restrict__ Q, const int* __restrict__ mask,
            const float* __restrict__ gamma, const float* __restrict__ beta,
            float* __restrict__ out)
{
    extern __shared__ float sm[];
    const int tid = threadIdx.x, warp = tid >> 5, lane = tid & 31;
    const int g = lane >> 2, tg = lane & 3;
    const int wm = warp >> 2, wn = warp & 3;     // 4x4 warp grid
    const int row0 = wm * 32, col0 = wn * 16;    // GEMM1 warp tile 32x16
    const int qt = blockIdx.x, bh = blockIdx.y;
    const size_t bho = (size_t)bh * Ldim * Dd;
    const uint32_t sb = (uint32_t)__cvta_generic_to_shared(sm);
    const int srcA = (lane & ~3) | (tg >> 1);    // quad-local shuffle sources
    const int srcB = srcA + 2;
    const bool hiSel = (tg & 1);

    // ---- stage Q (tf32) ----
    const float* qp = Q + bho + (size_t)qt * BM * Dd;
    #pragma unroll
    for (int j = 0; j < 4; ++j) {
        int idx = tid + j * 512, r = idx >> 4, c = (idx & 15) << 2;
        float4 t = *(const float4*)(qp + (size_t)r * Dd + c);
        *(float4*)(sm + QS + r * STR + c) = make_float4(tf(t.x), tf(t.y), tf(t.z), tf(t.w));
    }
    // ---- prefetch k-tile 0 ----
    {
        const float* kp = g_kt + bho;
        const float* vp = g_vt + bho;
        #pragma unroll
        for (int j = 0; j < 2; ++j) {
            int ch = tid + j * 512, r = ch >> 4, c = (ch & 15) << 2;
            cpa16(sb + (uint32_t)(KS_ + r * STR + c) * 4u, kp + (size_t)r * Dd + c);
            cpa16(sb + (uint32_t)(VS_ + r * STR + c) * 4u, vp + (size_t)r * Dd + c);
        }
        cp_commit();
    }

    float o[2][8][4] = {};   // partial O: 32 rows x 64 cols over this warp's k-slice

    for (int kt = 0; kt < NT; ++kt) {
        const int buf = kt & 1;
        cp_wait0();
        __syncthreads();   // tile kt resident; all warps done reading buf^1

        if (kt + 1 < NT) {
            const float* kp = g_kt + bho + (size_t)(kt + 1) * BN * Dd;
            const float* vp = g_vt + bho + (size_t)(kt + 1) * BN * Dd;
            const int bo = (buf ^ 1) * BUFF;
            #pragma unroll
            for (int j = 0; j < 2; ++j) {
                int ch = tid + j * 512, r = ch >> 4, c = (ch & 15) << 2;
                cpa16(sb + (uint32_t)(KS_ + bo + r * STR + c) * 4u, kp + (size_t)r * Dd + c);
                cpa16(sb + (uint32_t)(VS_ + bo + r * STR + c) * 4u, vp + (size_t)r * Dd + c);
            }
            cp_commit();
        }

        const float* Ksb = sm + KS_ + buf * BUFF;
        const float* Vsb = sm + VS_ + buf * BUFF;

        // ---- GEMM1: S(32x16) = Q @ K^T over D=64 ----
        float s[2][2][4] = {};
        #pragma unroll
        for (int kk = 0; kk < Dd; kk += 8) {
            uint32_t a[2][4], b[2][2];
            #pragma unroll
            for (int mi = 0; mi < 2; ++mi) {
                const float* p = sm + QS + (row0 + mi * 16 + g) * STR + kk + tg;
                a[mi][0] = __float_as_uint(p[0]);
                a[mi][1] = __float_as_uint(p[8 * STR]);
                a[mi][2] = __float_as_uint(p[4]);
                a[mi][3] = __float_as_uint(p[8 * STR + 4]);
            }
            #pragma unroll
            for (int nj = 0; nj < 2; ++nj) {
                const float* p = Ksb + (col0 + nj * 8 + g) * STR + kk + tg;
                b[nj][0] = __float_as_uint(p[0]);
                b[nj][1] = __float_as_uint(p[4]);
            }
            #pragma unroll
            for (int mi = 0; mi < 2; ++mi)
                #pragma unroll
                for (int nj = 0; nj < 2; ++nj)
                    mma8(s[mi][nj], a[mi], b[nj]);
        }

        // ---- mask in fp32 (-1e4 exact in tf32), requantize, stay in regs ----
        #pragma unroll
        for (int mi = 0; mi < 2; ++mi) {
            #pragma unroll
            for (int nj = 0; nj < 2; ++nj) {
                const int rl = row0 + mi * 16 + g;
                const int cl = col0 + nj * 8 + 2 * tg;
                const int gq = qt * BM + rl, gc = kt * BN + cl;
                int2 m0 = *(const int2*)(mask + (size_t)gq * Ldim + gc);
                int2 m1 = *(const int2*)(mask + (size_t)(gq + 8) * Ldim + gc);
                s[mi][nj][0] = tf(m0.x ? s[mi][nj][0] : -10000.0f);
                s[mi][nj][1] = tf(m0.y ? s[mi][nj][1] : -10000.0f);
                s[mi][nj][2] = tf(m1.x ? s[mi][nj][2] : -10000.0f);
                s[mi][nj][3] = tf(m1.y ? s[mi][nj][3] : -10000.0f);
            }
        }

        // ---- GEMM2: O_partial(32x64) += S_slice @ V[16 k-rows, 64 cols] ----
        #pragma unroll
        for (int ks = 0; ks < 2; ++ks) {
            // permute accumulator frags -> A frags (intra-quad shfl)
            uint32_t a[2][4];
            #pragma unroll
            for (int mi = 0; mi < 2; ++mi) {
                float lo, hi;
                lo = __shfl_sync(0xFFFFFFFFu, s[mi][ks][0], srcA);
                hi = __shfl_sync(0xFFFFFFFFu, s[mi][ks][1], srcA);
                a[mi][0] = __float_as_uint(hiSel ? hi : lo);
                lo = __shfl_sync(0xFFFFFFFFu, s[mi][ks][2], srcA);
                hi = __shfl_sync(0xFFFFFFFFu, s[mi][ks][3], srcA);
                a[mi][1] = __float_as_uint(hiSel ? hi : lo);
                lo = __shfl_sync(0xFFFFFFFFu, s[mi][ks][0], srcB);
                hi = __shfl_sync(0xFFFFFFFFu, s[mi][ks][1], srcB);
                a[mi][2] = __float_as_uint(hiSel ? hi : lo);
                lo = __shfl_sync(0xFFFFFFFFu, s[mi][ks][2], srcB);
                hi = __shfl_sync(0xFFFFFFFFu, s[mi][ks][3], srcB);
                a[mi][3] = __float_as_uint(hiSel ? hi : lo);
            }
            const int kv = col0 + ks * 8;   // V row base for this k-slice
            #pragma unroll
            for (int nj = 0; nj < 8; ++nj) {
                uint32_t b[2];
                const float* p = Vsb + (kv + tg) * STR + nj * 8 + g;
                b[0] = __float_as_uint(p[0]);
                b[1] = __float_as_uint(p[4 * STR]);
                mma8(o[0][nj], a[0], b);
                mma8(o[1][nj], a[1], b);
            }
        }
    }

    // ---- reduce partial O across the 4 wn-warps into QS region ----
    __syncthreads();   // Q reads done; reuse QS as O buffer
    #pragma unroll
    for (int w = 0; w < 4; ++w) {
        if (wn == w) {
            #pragma unroll
            for (int mi = 0; mi < 2; ++mi) {
                #pragma unroll
                for (int nj = 0; nj < 8; ++nj) {
                    const int rl = row0 + mi * 16 + g;
                    const int cl = nj * 8 + 2 * tg;
                    float* p0 = sm + QS + rl * STR + cl;
                    float* p1 = sm + QS + (rl + 8) * STR + cl;
                    if (w == 0) {
                        *(float2*)p0 = make_float2(o[mi][nj][0], o[mi][nj][1]);
                        *(float2*)p1 = make_float2(o[mi][nj][2], o[mi][nj][3]);
                    } else {
                        float2 t0 = *(float2*)p0, t1 = *(float2*)p1;
                        t0.x += o[mi][nj][0]; t0.y += o[mi][nj][1];
                        t1.x += o[mi][nj][2]; t1.y += o[mi][nj][3];
                        *(float2*)p0 = t0;
                        *(float2*)p1 = t1;
                    }
                }
            }
        }
        __syncthreads();
    }

    // ---- LayerNorm over D=64, one thread per row ----
    if (tid < BM) {
        const float* rowp = sm + QS + tid * STR;
        float x[Dd]; float sum = 0.0f;
        #pragma unroll
        for (int c = 0; c < Dd; c += 4) {
            float4 t = *(const float4*)(rowp + c);
            x[c] = t.x; x[c+1] = t.y; x[c+2] = t.z; x[c+3] = t.w;
            sum += t.x + t.y + t.z + t.w;
        }
        const float mean = sum * (1.0f / Dd);
        float var = 0.0f;
        #pragma unroll
        for (int c = 0; c < Dd; ++c) { float d = x[c] - mean; var += d * d; }
        const float inv = rsqrtf(var * (1.0f / Dd) + 1e-12f);
        float* op = out + bho + (size_t)(qt * BM + tid) * Dd;
        #pragma unroll
        for (int c = 0; c < Dd; c += 4) {
            float4 t = make_float4(
                (x[c]   - mean) * inv * __ldg(gamma + c)     + __ldg(beta + c),
                (x[c+1] - mean) * inv * __ldg(gamma + c + 1) + __ldg(beta + c + 1),
                (x[c+2] - mean) * inv * __ldg(gamma + c + 2) + __ldg(beta + c + 2),
                (x[c+3] - mean) * inv * __ldg(gamma + c + 3) + __ldg(beta + c + 3));
            *(float4*)(op + c) = t;
        }
    }
}

extern "C" void kernel_launch(void* const* d_in, const int* in_sizes, int n_in,
                              void* d_out, int out_size)
{
    const float* q     = (const float*)d_in[0];
    const float* k     = (const float*)d_in[1];
    const float* v     = (const float*)d_in[2];
    const int*   mask  = (const int*)  d_in[3];
    const float* gamma = (const float*)d_in[4];
    const float* beta  = (const float*)d_in[5];
    float* out = (float*)d_out;

    const int bh = in_sizes[0] / (Ldim * Dd);   // 24
    const int n4 = bh * Ldim * Dd / 4;

    cvt_kv_k<<<(n4 + 255) / 256, 256>>>(k, v, n4);

    cudaFuncSetAttribute(attn_k, cudaFuncAttributeMaxDynamicSharedMemorySize,
                         SMEMF * (int)sizeof(float));
    attn_k<<<dim3(Ldim / BM, bh), 512, SMEMF * (int)sizeof(float)>>>(
        q, mask, gamma, beta, out);
}

// round 6
// speedup vs baseline: 3.9998x; 2.0317x over previous
#include <cuda_runtime.h>
#include <cuda_fp16.h>
#include <cstdint>

// NormAttention, sm_103 legacy mma.sync path (tcgen05 rejected by toolchain, R3).
// R6: fp16 m16n8k16 (10-bit mantissa == tf32; -10000 exact in fp16), fp32 accum.
// GEMM1 accum == GEMM2 A-frag natively (no shfl). All smem operands packed
// fp16x2 in a bank-conflict-free 40-word-row layout; every load is LDS.64.

namespace {
constexpr int Ldim = 2048, Dd = 64, BM = 128, BN = 64, NT = Ldim / BN;
constexpr int ROWW = 40;                 // 32-bit words per packed row
constexpr int QW = 0;                    // Q: 128 x 40 words
constexpr int KW = QW + BM * ROWW;       // K: 2 x 64 x 40
constexpr int VW = KW + 2 * BN * ROWW;   // V: 2 x 64 x 40
constexpr int SMEMW = VW + 2 * BN * ROWW;  // 15360 words = 61440 B
constexpr int KBUF = BN * ROWW;          // 2560 words per buffer
constexpr int OSTR = 68;                 // fp32 O-reduce row stride

// packed word index for element-pair c2 (=col/2) of a row
__device__ __forceinline__ int fw(int c2) { return (c2 & 3) * 10 + (c2 >> 2); }

__device__ __forceinline__ uint32_t pk2(float x, float y) {
    __half2 h = __floats2half2_rn(x, y);
    return *reinterpret_cast<uint32_t*>(&h);
}
__device__ __forceinline__ void mma16(float c[4], const uint32_t a[4], const uint32_t b[2]) {
    asm volatile(
        "mma.sync.aligned.m16n8k16.row.col.f32.f16.f16.f32 "
        "{%0,%1,%2,%3},{%4,%5,%6,%7},{%8,%9},{%0,%1,%2,%3};"
        : "+f"(c[0]), "+f"(c[1]), "+f"(c[2]), "+f"(c[3])
        : "r"(a[0]), "r"(a[1]), "r"(a[2]), "r"(a[3]), "r"(b[0]), "r"(b[1]));
}
__device__ __forceinline__ void cpa16(uint32_t s, const void* g) {
    asm volatile("cp.async.cg.shared.global [%0],[%1],16;" :: "r"(s), "l"(g));
}
__device__ __forceinline__ void cp_commit() { asm volatile("cp.async.commit_group;"); }
__device__ __forceinline__ void cp_wait0()  { asm volatile("cp.async.wait_group 0;"); }
} // namespace

// device scratch (static; no runtime alloc)
__device__ __align__(16) uint32_t g_kh[24 * Ldim * ROWW];        // packed fp16x2 K rows
__device__ __align__(16) uint32_t g_vh[24 * NT * BN * ROWW];     // packed fp16x2 V^T per tile
__device__ __align__(16) uint32_t g_mb[Ldim * (Ldim / 32)];      // packed mask bits

// ---- prelude: K rows -> packed fp16x2 layout ----
__global__ void cvt_k_k(const float* __restrict__ K, int total) {
    int idx = blockIdx.x * blockDim.x + threadIdx.x;
    if (idx >= total) return;                 // total = 24*2048*32
    int r = idx >> 5, c2 = idx & 31;
    float2 t = *(const float2*)(K + (size_t)r * Dd + 2 * c2);
    g_kh[r * ROWW + fw(c2)] = pk2(t.x, t.y);
}
// ---- prelude: V tile transpose -> packed fp16x2 pairs (row-pairs along k) ----
__global__ void cvt_v_k(const float* __restrict__ V) {
    __shared__ float t[64][65];
    const int kt = blockIdx.x, bh = blockIdx.y, tid = threadIdx.x;
    const float* vp = V + (size_t)bh * Ldim * Dd + (size_t)kt * BN * Dd;
    #pragma unroll
    for (int i = 0; i < 16; ++i) {
        int idx = tid + i * 256, r = idx >> 6, n = idx & 63;
        t[r][n] = vp[(size_t)r * Dd + n];
    }
    __syncthreads();
    uint32_t* dst = g_vh + (size_t)(bh * NT + kt) * BN * ROWW;
    #pragma unroll
    for (int i = 0; i < 8; ++i) {
        int idx = tid + i * 256, n = idx >> 5, p = idx & 31;
        dst[n * ROWW + fw(p)] = pk2(t[2 * p][n], t[2 * p + 1][n]);
    }
}
// ---- prelude: pack mask bits ----
__global__ void pack_mask_k(const int* __restrict__ mask) {
    int w = (blockIdx.x * blockDim.x + threadIdx.x) >> 5, l = threadIdx.x & 31;
    if (w >= Ldim) return;
    const int* mr = mask + (size_t)w * Ldim;
    uint32_t* orow = g_mb + (size_t)w * (Ldim / 32);
    for (int i = 0; i < Ldim / 32; ++i) {
        uint32_t b = __ballot_sync(0xFFFFFFFFu, mr[i * 32 + l] != 0);
        if (l == 0) orow[i] = b;
    }
}

__global__ __launch_bounds__(512, 1)
void attn_k(const float* __restrict__ Q,
            const float* __restrict__ gamma, const float* __restrict__ beta,
            float* __restrict__ out)
{
    extern __shared__ uint32_t sm32[];
    const int tid = threadIdx.x, warp = tid >> 5, lane = tid & 31;
    const int g = lane >> 2, tg = lane & 3;
    const int wm = warp >> 2, wn = warp & 3;      // 4x4 warp grid
    const int row0 = wm * 32, col0 = wn * 16;     // warp: S tile 32 rows x 16 cols
    const int qt = blockIdx.x, bh = blockIdx.y;
    const size_t bho = (size_t)bh * Ldim * Dd;
    const uint32_t sb = (uint32_t)__cvta_generic_to_shared(sm32);

    // ---- stage Q packed fp16x2 ----
    const float* qp = Q + bho + (size_t)qt * BM * Dd;
    #pragma unroll
    for (int i = 0; i < 8; ++i) {
        int idx = tid + i * 512, r = idx >> 5, c2 = idx & 31;
        float2 t = *(const float2*)(qp + (size_t)r * Dd + 2 * c2);
        sm32[QW + r * ROWW + fw(c2)] = pk2(t.x, t.y);
    }
    // ---- prefetch tile 0 ----
    {
        const uint32_t* kbase = g_kh + (size_t)bh * Ldim * ROWW;
        const uint32_t* vbase = g_vh + (size_t)bh * NT * BN * ROWW;
        #pragma unroll
        for (int j3 = 0; j3 < 3; ++j3) {
            int j = tid + j3 * 512;
            if (j < 1280) {
                bool isv = j >= 640; int jj = isv ? j - 640 : j;
                int n = jj / 10, c = jj - n * 10;
                const uint32_t* src = (isv ? vbase : kbase) + n * ROWW + c * 4;
                cpa16(sb + (uint32_t)((isv ? VW : KW) + n * ROWW + c * 4) * 4u, src);
            }
        }
        cp_commit();
    }

    float o[2][8][4] = {};   // partial O 32x64 over this warp's 16-wide k-slice
    const int wi_base = (wn >> 1);            // mask word within tile
    const int posb = (wn & 1) * 16 + 2 * tg;  // bit base

    for (int kt = 0; kt < NT; ++kt) {
        const int buf = kt & 1;
        cp_wait0();
        __syncthreads();

        if (kt + 1 < NT) {
            const uint32_t* kbase = g_kh + (size_t)(bh * Ldim + (kt + 1) * BN) * ROWW;
            const uint32_t* vbase = g_vh + (size_t)(bh * NT + kt + 1) * BN * ROWW;
            const int bo = (buf ^ 1) * KBUF;
            #pragma unroll
            for (int j3 = 0; j3 < 3; ++j3) {
                int j = tid + j3 * 512;
                if (j < 1280) {
                    bool isv = j >= 640; int jj = isv ? j - 640 : j;
                    int n = jj / 10, c = jj - n * 10;
                    const uint32_t* src = (isv ? vbase : kbase) + n * ROWW + c * 4;
                    cpa16(sb + (uint32_t)((isv ? VW : KW) + bo + n * ROWW + c * 4) * 4u, src);
                }
            }
            cp_commit();
        }

        const uint32_t* Ksb = sm32 + KW + buf * KBUF;
        const uint32_t* Vsb = sm32 + VW + buf * KBUF;

        // ---- GEMM1: S(32x16) = Q @ K^T over D=64 (4 k-steps of 16) ----
        float s[2][2][4] = {};
        #pragma unroll
        for (int m = 0; m < 4; ++m) {
            uint32_t a[2][4];
            #pragma unroll
            for (int mi = 0; mi < 2; ++mi) {
                int r0 = row0 + mi * 16 + g;
                uint2 t0 = *(const uint2*)(sm32 + QW + r0 * ROWW + tg * 10 + 2 * m);
                uint2 t1 = *(const uint2*)(sm32 + QW + (r0 + 8) * ROWW + tg * 10 + 2 * m);
                a[mi][0] = t0.x; a[mi][2] = t0.y;
                a[mi][1] = t1.x; a[mi][3] = t1.y;
            }
            #pragma unroll
            for (int nj = 0; nj < 2; ++nj) {
                int n = col0 + nj * 8 + g;
                uint2 tb = *(const uint2*)(Ksb + n * ROWW + tg * 10 + 2 * m);
                uint32_t b[2] = {tb.x, tb.y};
                mma16(s[0][nj], a[0], b);
                mma16(s[1][nj], a[1], b);
            }
        }

        // ---- mask (fp32; -1e4 exact in fp16) and pack -> GEMM2 A-frags ----
        uint32_t af[2][4];
        #pragma unroll
        for (int mi = 0; mi < 2; ++mi) {
            const int gq = qt * BM + row0 + mi * 16 + g;
            uint32_t m0 = g_mb[(size_t)gq * 64 + kt * 2 + wi_base];
            uint32_t m1 = g_mb[(size_t)(gq + 8) * 64 + kt * 2 + wi_base];
            #pragma unroll
            for (int nj = 0; nj < 2; ++nj) {
                const int pos = posb + nj * 8;
                float f0 = ((m0 >> pos) & 1)       ? s[mi][nj][0] : -10000.0f;
                float f1 = ((m0 >> (pos + 1)) & 1) ? s[mi][nj][1] : -10000.0f;
                float f2 = ((m1 >> pos) & 1)       ? s[mi][nj][2] : -10000.0f;
                float f3 = ((m1 >> (pos + 1)) & 1) ? s[mi][nj][3] : -10000.0f;
                af[mi][nj * 2]     = pk2(f0, f1);   // rows g
                af[mi][nj * 2 + 1] = pk2(f2, f3);   // rows g+8
            }
        }

        // ---- GEMM2: O_partial(32x64) += S_slice(16) @ V ----
        #pragma unroll
        for (int nj = 0; nj < 8; ++nj) {
            int n = nj * 8 + g;
            uint2 tb = *(const uint2*)(Vsb + n * ROWW + tg * 10 + 2 * wn);
            uint32_t b[2] = {tb.x, tb.y};
            mma16(o[0][nj], af[0], b);
            mma16(o[1][nj], af[1], b);
        }
    }

    // ---- reduce partial O across the 4 wn-warps (reuse smem) ----
    float* smf = reinterpret_cast<float*>(sm32);
    __syncthreads();
    #pragma unroll
    for (int w = 0; w < 4; ++w) {
        if (wn == w) {
            #pragma unroll
            for (int mi = 0; mi < 2; ++mi) {
                #pragma unroll
                for (int nj = 0; nj < 8; ++nj) {
                    const int rl = row0 + mi * 16 + g;
                    const int cl = nj * 8 + 2 * tg;
                    float* p0 = smf + rl * OSTR + cl;
                    float* p1 = smf + (rl + 8) * OSTR + cl;
                    if (w == 0) {
                        *(float2*)p0 = make_float2(o[mi][nj][0], o[mi][nj][1]);
                        *(float2*)p1 = make_float2(o[mi][nj][2], o[mi][nj][3]);
                    } else {
                        float2 t0 = *(float2*)p0, t1 = *(float2*)p1;
                        t0.x += o[mi][nj][0]; t0.y += o[mi][nj][1];
                        t1.x += o[mi][nj][2]; t1.y += o[mi][nj][3];
                        *(float2*)p0 = t0;
                        *(float2*)p1 = t1;
                    }
                }
            }
        }
        __syncthreads();
    }

    // ---- LayerNorm over D=64 ----
    if (tid < BM) {
        const float* rowp = smf + tid * OSTR;
        float x[Dd]; float sum = 0.0f;
        #pragma unroll
        for (int c = 0; c < Dd; c += 4) {
            float4 t = *(const float4*)(rowp + c);
            x[c] = t.x; x[c+1] = t.y; x[c+2] = t.z; x[c+3] = t.w;
            sum += t.x + t.y + t.z + t.w;
        }
        const float mean = sum * (1.0f / Dd);
        float var = 0.0f;
        #pragma unroll
        for (int c = 0; c < Dd; ++c) { float d = x[c] - mean; var += d * d; }
        const float inv = rsqrtf(var * (1.0f / Dd) + 1e-12f);
        float* op = out + bho + (size_t)(qt * BM + tid) * Dd;
        #pragma unroll
        for (int c = 0; c < Dd; c += 4) {
            float4 t = make_float4(
                (x[c]   - mean) * inv * __ldg(gamma + c)     + __ldg(beta + c),
                (x[c+1] - mean) * inv * __ldg(gamma + c + 1) + __ldg(beta + c + 1),
                (x[c+2] - mean) * inv * __ldg(gamma + c + 2) + __ldg(beta + c + 2),
                (x[c+3] - mean) * inv * __ldg(gamma + c + 3) + __ldg(beta + c + 3));
            *(float4*)(op + c) = t;
        }
    }
}

extern "C" void kernel_launch(void* const* d_in, const int* in_sizes, int n_in,
                              void* d_out, int out_size)
{
    const float* q     = (const float*)d_in[0];
    const float* k     = (const float*)d_in[1];
    const float* v     = (const float*)d_in[2];
    const int*   mask  = (const int*)  d_in[3];
    const float* gamma = (const float*)d_in[4];
    const float* beta  = (const float*)d_in[5];
    float* out = (float*)d_out;

    const int bh = in_sizes[0] / (Ldim * Dd);   // 24
    const int ktotal = bh * Ldim * (Dd / 2);

    cvt_k_k<<<(ktotal + 255) / 256, 256>>>(k, ktotal);
    cvt_v_k<<<dim3(NT, bh), 256>>>(v);
    pack_mask_k<<<Ldim * 32 / 256, 256>>>(mask);

    cudaFuncSetAttribute(attn_k, cudaFuncAttributeMaxDynamicSharedMemorySize,
                         SMEMW * (int)sizeof(uint32_t));
    attn_k<<<dim3(Ldim / BM, bh), 512, SMEMW * (int)sizeof(uint32_t)>>>(
        q, gamma, beta, out);
}

// round 7
// speedup vs baseline: 5.2612x; 1.3154x over previous
#include <cuda_runtime.h>
#include <cuda_fp16.h>
#include <cstdint>

// NormAttention, sm_103 legacy mma.sync path. R7: fp16 m16n8k16 + ldmatrix.x4
// operand loads from XOR-swizzled 128B-row smem tiles; 256-thr CTAs, 2 CTAs/SM.
// S stays in registers between GEMMs (accum frag == A frag natively).

namespace {
constexpr int Ldim = 2048, Dd = 64, BM = 128, BN = 64, NT = Ldim / BN;
// smem word layout: Q[128 rows x 32 words] | K 2x[64x32] | V 2x[64x32]
constexpr int KB0 = 4096, VB0 = 8192, SMEMW = 12288;   // 49152 B
constexpr int OSTR = 68;                               // fp32 O-reduce stride

__device__ __forceinline__ uint32_t pk2(float x, float y) {
    __half2 h = __floats2half2_rn(x, y);
    return *reinterpret_cast<uint32_t*>(&h);
}
__device__ __forceinline__ void mma16(float c[4], const uint32_t a[4], const uint32_t b[2]) {
    asm volatile(
        "mma.sync.aligned.m16n8k16.row.col.f32.f16.f16.f32 "
        "{%0,%1,%2,%3},{%4,%5,%6,%7},{%8,%9},{%0,%1,%2,%3};"
        : "+f"(c[0]), "+f"(c[1]), "+f"(c[2]), "+f"(c[3])
        : "r"(a[0]), "r"(a[1]), "r"(a[2]), "r"(a[3]), "r"(b[0]), "r"(b[1]));
}
__device__ __forceinline__ void ldsm4(uint32_t r[4], uint32_t addr) {
    asm volatile("ldmatrix.sync.aligned.m8n8.x4.shared.b16 {%0,%1,%2,%3},[%4];"
        : "=r"(r[0]), "=r"(r[1]), "=r"(r[2]), "=r"(r[3]) : "r"(addr));
}
__device__ __forceinline__ void cpa16(uint32_t s, const void* g) {
    asm volatile("cp.async.cg.shared.global [%0],[%1],16;" :: "r"(s), "l"(g));
}
__device__ __forceinline__ void cp_commit() { asm volatile("cp.async.commit_group;"); }
__device__ __forceinline__ void cp_wait0()  { asm volatile("cp.async.wait_group 0;"); }
} // namespace

// static device scratch
__device__ __align__(16) uint32_t g_kh[24 * Ldim * 32];   // K packed fp16x2, [row][32w]
__device__ __align__(16) uint32_t g_vh[24 * Ldim * 32];   // V^T per 64-tile: [bh][kt][n(64)][32w]
__device__ __align__(16) uint32_t g_mb[Ldim * 64];        // mask bits [row][64 words]

__global__ void cvt_k_k(const float* __restrict__ K, int total) {
    int idx = blockIdx.x * blockDim.x + threadIdx.x;
    if (idx >= total) return;                 // total = 24*2048*32
    float2 t = *(const float2*)(K + 2 * (size_t)idx);
    g_kh[idx] = pk2(t.x, t.y);
}
__global__ void cvt_v_k(const float* __restrict__ V) {
    __shared__ float t[64][65];
    const int kt = blockIdx.x, bh = blockIdx.y, tid = threadIdx.x;
    const float* vp = V + (size_t)bh * Ldim * Dd + (size_t)kt * 64 * Dd;
    #pragma unroll
    for (int i = 0; i < 16; ++i) {
        int idx = tid + i * 256;
        t[idx >> 6][idx & 63] = vp[idx];
    }
    __syncthreads();
    uint32_t* dst = g_vh + (size_t)(bh * NT + kt) * 64 * 32;
    #pragma unroll
    for (int i = 0; i < 8; ++i) {
        int idx = tid + i * 256, n = idx >> 5, p = idx & 31;
        dst[n * 32 + p] = pk2(t[2 * p][n], t[2 * p + 1][n]);
    }
}
__global__ void pack_mask_k(const int* __restrict__ mask) {
    int w = (blockIdx.x * blockDim.x + threadIdx.x) >> 5, l = threadIdx.x & 31;
    if (w >= Ldim) return;
    const int* mr = mask + (size_t)w * Ldim;
    uint32_t* orow = g_mb + (size_t)w * 64;
    for (int i = 0; i < 64; ++i) {
        uint32_t b = __ballot_sync(0xFFFFFFFFu, mr[i * 32 + l] != 0);
        if (l == 0) orow[i] = b;
    }
}

__global__ __launch_bounds__(256, 2)
void attn_k(const float* __restrict__ Q,
            const float* __restrict__ gamma, const float* __restrict__ beta,
            float* __restrict__ out)
{
    extern __shared__ uint32_t sm32[];
    const int tid = threadIdx.x, warp = tid >> 5, lane = tid & 31;
    const int g = lane >> 2, tg = lane & 3;
    const int wm = warp >> 1, wn = warp & 1;      // 4x2 warp grid
    const int row0 = wm * 32, col0 = wn * 32;     // warp: 32 rows, 32-wide k-slice
    const int qt = blockIdx.x, bh = blockIdx.y;
    const size_t bho = (size_t)bh * Ldim * Dd;
    const uint32_t sb = (uint32_t)__cvta_generic_to_shared(sm32);

    // per-lane ldmatrix geometry (all tile rows are 128B; phase = lane&7)
    const int l7 = lane & 7;
    const int csA = lane >> 4;                    // A: chunk-half select
    const int rA8 = ((lane >> 3) & 1) * 8 + l7;   // A: row-within-16
    const int csB = (lane >> 3) & 1;              // B: chunk-half select
    const int rB8 = ((lane >> 4) & 1) * 8 + l7;   // B: row-within-16
    const uint32_t qb0 = sb + (uint32_t)(row0 + rA8) * 128;        // Q mi=0
    const uint32_t qb1 = qb0 + 16 * 128;                           // Q mi=1
    const uint32_t kb0 = (uint32_t)(col0 + rB8) * 128;             // K njp=0 (tile-rel)
    const uint32_t vb_ = (uint32_t)rB8 * 128;                      // V njp=0 (tile-rel)

    // ---- stage Q packed fp16x2 (swizzled chunks) ----
    const float* qp = Q + bho + (size_t)qt * BM * Dd;
    #pragma unroll
    for (int j = 0; j < 8; ++j) {
        int i = tid + j * 256, r = i >> 4, h = i & 15;
        float4 t = *(const float4*)(qp + (size_t)r * Dd + 4 * h);
        int c = h >> 1, w = (h & 1) * 2;
        *(uint2*)(sm32 + r * 32 + ((c ^ (r & 7)) << 2) + w) =
            make_uint2(pk2(t.x, t.y), pk2(t.z, t.w));
    }
    // ---- prefetch tile 0 ----
    {
        const uint32_t* kg = g_kh + (size_t)bh * Ldim * 32;
        const uint32_t* vg = g_vh + (size_t)bh * Ldim * 32;
        #pragma unroll
        for (int j = 0; j < 4; ++j) {
            int ch = tid + j * 256;               // 0..511 K, 512..1023 V
            int r = (ch & 511) >> 3, c = ch & 7;
            const uint32_t* src = (ch < 512 ? kg : vg) + r * 32 + c * 4;
            int base = (ch < 512 ? KB0 : VB0);
            cpa16(sb + (uint32_t)(base + r * 32 + ((c ^ (r & 7)) << 2)) * 4u, src);
        }
        cp_commit();
    }

    float o[2][8][4] = {};   // partial O 32x64 over this warp's 32-wide k-slice

    for (int kt = 0; kt < NT; ++kt) {
        const int buf = kt & 1;
        cp_wait0();
        __syncthreads();

        if (kt + 1 < NT) {
            const uint32_t* kg = g_kh + ((size_t)bh * Ldim + (kt + 1) * 64) * 32;
            const uint32_t* vg = g_vh + ((size_t)bh * NT + kt + 1) * 64 * 32;
            const int bo = (buf ^ 1) * 2048;
            #pragma unroll
            for (int j = 0; j < 4; ++j) {
                int ch = tid + j * 256;
                int r = (ch & 511) >> 3, c = ch & 7;
                const uint32_t* src = (ch < 512 ? kg : vg) + r * 32 + c * 4;
                int base = (ch < 512 ? KB0 : VB0) + bo;
                cpa16(sb + (uint32_t)(base + r * 32 + ((c ^ (r & 7)) << 2)) * 4u, src);
            }
            cp_commit();
        }

        const uint32_t kbuf = sb + (uint32_t)(KB0 + buf * 2048) * 4u;
        const uint32_t vbuf = sb + (uint32_t)(VB0 + buf * 2048) * 4u;

        // ---- GEMM1: S(32x32) = Q @ K^T over D=64 (4 k-steps) ----
        float s[2][4][4] = {};
        #pragma unroll
        for (int m = 0; m < 4; ++m) {
            const uint32_t cxa = (uint32_t)(((2 * m + csA) ^ l7) << 4);
            const uint32_t cxb = (uint32_t)(((2 * m + csB) ^ l7) << 4);
            uint32_t a0[4], a1[4], b0[4], b1[4];
            ldsm4(a0, qb0 + cxa);
            ldsm4(a1, qb1 + cxa);
            ldsm4(b0, kbuf + kb0 + cxb);            // nj0, nj1
            ldsm4(b1, kbuf + kb0 + 16 * 128 + cxb); // nj2, nj3
            mma16(s[0][0], a0, b0);     mma16(s[0][1], a0, b0 + 2);
            mma16(s[0][2], a0, b1);     mma16(s[0][3], a0, b1 + 2);
            mma16(s[1][0], a1, b0);     mma16(s[1][1], a1, b0 + 2);
            mma16(s[1][2], a1, b1);     mma16(s[1][3], a1, b1 + 2);
        }

        // ---- mask in fp32 (-1e4 exact in fp16) ----
        #pragma unroll
        for (int mi = 0; mi < 2; ++mi) {
            const int gq = qt * BM + row0 + mi * 16 + g;
            const uint32_t m0 = g_mb[(size_t)gq * 64 + kt * 2 + wn];
            const uint32_t m1 = g_mb[(size_t)(gq + 8) * 64 + kt * 2 + wn];
            #pragma unroll
            for (int nj = 0; nj < 4; ++nj) {
                const int pos = nj * 8 + 2 * tg;
                s[mi][nj][0] = ((m0 >> pos) & 1)       ? s[mi][nj][0] : -10000.0f;
                s[mi][nj][1] = ((m0 >> (pos + 1)) & 1) ? s[mi][nj][1] : -10000.0f;
                s[mi][nj][2] = ((m1 >> pos) & 1)       ? s[mi][nj][2] : -10000.0f;
                s[mi][nj][3] = ((m1 >> (pos + 1)) & 1) ? s[mi][nj][3] : -10000.0f;
            }
        }

        // ---- GEMM2: O_partial(32x64) += S_slice(32) @ V ----
        #pragma unroll
        for (int ks = 0; ks < 2; ++ks) {
            uint32_t a0[4] = { pk2(s[0][2*ks][0],   s[0][2*ks][1]),
                               pk2(s[0][2*ks][2],   s[0][2*ks][3]),
                               pk2(s[0][2*ks+1][0], s[0][2*ks+1][1]),
                               pk2(s[0][2*ks+1][2], s[0][2*ks+1][3]) };
            uint32_t a1[4] = { pk2(s[1][2*ks][0],   s[1][2*ks][1]),
                               pk2(s[1][2*ks][2],   s[1][2*ks][3]),
                               pk2(s[1][2*ks+1][0], s[1][2*ks+1][1]),
                               pk2(s[1][2*ks+1][2], s[1][2*ks+1][3]) };
            const uint32_t cx = (uint32_t)((((4 * wn + 2 * ks) + csB) ^ l7) << 4);
            #pragma unroll
            for (int njp = 0; njp < 4; ++njp) {
                uint32_t bv[4];
                ldsm4(bv, vbuf + vb_ + (uint32_t)njp * (16 * 128) + cx);
                mma16(o[0][2*njp],   a0, bv);     mma16(o[0][2*njp+1], a0, bv + 2);
                mma16(o[1][2*njp],   a1, bv);     mma16(o[1][2*njp+1], a1, bv + 2);
            }
        }
    }

    // ---- reduce partial O across the 2 wn-warps ----
    float* smf = reinterpret_cast<float*>(sm32);
    __syncthreads();
    #pragma unroll
    for (int w = 0; w < 2; ++w) {
        if (wn == w) {
            #pragma unroll
            for (int mi = 0; mi < 2; ++mi) {
                #pragma unroll
                for (int nj = 0; nj < 8; ++nj) {
                    const int rl = row0 + mi * 16 + g;
                    const int cl = nj * 8 + 2 * tg;
                    float* p0 = smf + rl * OSTR + cl;
                    float* p1 = smf + (rl + 8) * OSTR + cl;
                    if (w == 0) {
                        *(float2*)p0 = make_float2(o[mi][nj][0], o[mi][nj][1]);
                        *(float2*)p1 = make_float2(o[mi][nj][2], o[mi][nj][3]);
                    } else {
                        float2 t0 = *(float2*)p0, t1 = *(float2*)p1;
                        t0.x += o[mi][nj][0]; t0.y += o[mi][nj][1];
                        t1.x += o[mi][nj][2]; t1.y += o[mi][nj][3];
                        *(float2*)p0 = t0;
                        *(float2*)p1 = t1;
                    }
                }
            }
        }
        __syncthreads();
    }

    // ---- LayerNorm over D=64 ----
    if (tid < BM) {
        const float* rowp = smf + tid * OSTR;
        float x[Dd]; float sum = 0.0f;
        #pragma unroll
        for (int c = 0; c < Dd; c += 4) {
            float4 t = *(const float4*)(rowp + c);
            x[c] = t.x; x[c+1] = t.y; x[c+2] = t.z; x[c+3] = t.w;
            sum += t.x + t.y + t.z + t.w;
        }
        const float mean = sum * (1.0f / Dd);
        float var = 0.0f;
        #pragma unroll
        for (int c = 0; c < Dd; ++c) { float d = x[c] - mean; var += d * d; }
        const float inv = rsqrtf(var * (1.0f / Dd) + 1e-12f);
        float* op = out + bho + (size_t)(qt * BM + tid) * Dd;
        #pragma unroll
        for (int c = 0; c < Dd; c += 4) {
            float4 t = make_float4(
                (x[c]   - mean) * inv * __ldg(gamma + c)     + __ldg(beta + c),
                (x[c+1] - mean) * inv * __ldg(gamma + c + 1) + __ldg(beta + c + 1),
                (x[c+2] - mean) * inv * __ldg(gamma + c + 2) + __ldg(beta + c + 2),
                (x[c+3] - mean) * inv * __ldg(gamma + c + 3) + __ldg(beta + c + 3));
            *(float4*)(op + c) = t;
        }
    }
}

extern "C" void kernel_launch(void* const* d_in, const int* in_sizes, int n_in,
                              void* d_out, int out_size)
{
    const float* q     = (const float*)d_in[0];
    const float* k     = (const float*)d_in[1];
    const float* v     = (const float*)d_in[2];
    const int*   mask  = (const int*)  d_in[3];
    const float* gamma = (const float*)d_in[4];
    const float* beta  = (const float*)d_in[5];
    float* out = (float*)d_out;

    const int bh = in_sizes[0] / (Ldim * Dd);   // 24
    const int ktotal = bh * Ldim * 32;

    cvt_k_k<<<(ktotal + 255) / 256, 256>>>(k, ktotal);
    cvt_v_k<<<dim3(NT, bh), 256>>>(v);
    pack_mask_k<<<Ldim * 32 / 256, 256>>>(mask);

    cudaFuncSetAttribute(attn_k, cudaFuncAttributeMaxDynamicSharedMemorySize,
                         SMEMW * (int)sizeof(uint32_t));
    attn_k<<<dim3(Ldim / BM, bh), 256, SMEMW * (int)sizeof(uint32_t)>>>(
        q, gamma, beta, out);
}